// round 17
// baseline (speedup 1.0000x reference)
#include <cuda_runtime.h>
#include <cstddef>

// FusionAdjacency: Af = rownorm( sigmoid(g)*scatter(s) + (1-sigmoid(g))*scatter(t) )
//
// R14: assembled from measured-cheap pieces (parking abandoned — L2 writes
// back dirty lines eagerly on B300, proven R8/R11/R13):
//  K1: plain-store float4 fill of all 256 MB (last ~126 MB stays CLEAN-
//      resident in L2) + hist fold (proven free in R9).
//  K2: rowinv = guarded reciprocal; re-zero rowsum (graph-replay safe).
//  K3: scatter all edges, wide grid; ~50% of atomics hit clean-resident
//      lines (R7-K4 showed 11.5us vs 16us cold).

#define NN 8192

__device__ float g_rowsum[NN];  // zero at module load; K2 re-zeros each call
__device__ float g_rowinv[NN];

// ---------------------------------------------------------------- K1
__global__ __launch_bounds__(256) void k1_fill_hist(
        const int* __restrict__ rows_s, const float* __restrict__ vals_s, int Es,
        const int* __restrict__ rows_t, const float* __restrict__ vals_t, int Et,
        const float* __restrict__ gamma, float* __restrict__ out) {
    const int tid = blockIdx.x * blockDim.x + threadIdx.x;
    const int stride = gridDim.x * blockDim.x;

    // hist fold: <=1 edge per thread per list, fire-and-forget REDs into the
    // 32KB L2-hot rowsum array; drains underneath the fill stores.
    const float g = gamma[0];
    const float alpha = 1.0f / (1.0f + expf(-g));
    const float beta = 1.0f - alpha;
    for (int e = tid; e < Es; e += stride)
        atomicAdd(&g_rowsum[__ldg(&rows_s[e])], alpha * __ldg(&vals_s[e]));
    for (int e = tid; e < Et; e += stride)
        atomicAdd(&g_rowsum[__ldg(&rows_t[e])], beta * __ldg(&vals_t[e]));

    // plain (evict-normal) float4 fill: forward order, so the LAST ~126MB of
    // lines remain clean-resident in L2 for K3's atomics.
    float4* out4 = reinterpret_cast<float4*>(out);
    const int n4 = NN * (NN / 4);
    const float4 z = make_float4(0.f, 0.f, 0.f, 0.f);
    for (int i = tid; i < n4; i += stride) out4[i] = z;
}

// ---------------------------------------------------------------- K2
__global__ void k2_finalize() {
    int i = blockIdx.x * blockDim.x + threadIdx.x;
    if (i < NN) {
        float s = g_rowsum[i];
        g_rowinv[i] = (s == 0.0f) ? 1.0f : (1.0f / s);
        g_rowsum[i] = 0.0f;   // ready for next graph replay
    }
}

// ---------------------------------------------------------------- K3
// Dual independent load->scale->RED chains per iteration; wide grid for MLP.
__global__ __launch_bounds__(256) void k3_scatter(
        const int* __restrict__ rows_s, const int* __restrict__ cols_s,
        const float* __restrict__ vals_s, int Es,
        const int* __restrict__ rows_t, const int* __restrict__ cols_t,
        const float* __restrict__ vals_t, int Et,
        const float* __restrict__ gamma, float* __restrict__ out) {
    const float g = gamma[0];
    const float alpha = 1.0f / (1.0f + expf(-g));
    const float beta = 1.0f - alpha;
    const int tid = blockIdx.x * blockDim.x + threadIdx.x;
    const int stride = gridDim.x * blockDim.x;

    const int n = (Es > Et) ? Es : Et;
    for (int e = tid; e < n; e += stride) {
        int rs = 0, cs = 0;  float vs = 0.0f;
        if (e < Es) {
            rs = __ldg(&rows_s[e]);
            cs = __ldg(&cols_s[e]);
            vs = __ldg(&vals_s[e]);
        }
        int rt = 0, ct = 0;  float vt = 0.0f;
        if (e < Et) {
            rt = __ldg(&rows_t[e]);
            ct = __ldg(&cols_t[e]);
            vt = __ldg(&vals_t[e]);
        }
        float invs = g_rowinv[rs];
        float invt = g_rowinv[rt];
        if (e < Es) atomicAdd(&out[((size_t)rs << 13) + cs], alpha * vs * invs);
        if (e < Et) atomicAdd(&out[((size_t)rt << 13) + ct], beta * vt * invt);
    }
}

// ---------------------------------------------------------------- launch
extern "C" void kernel_launch(void* const* d_in, const int* in_sizes, int n_in,
                              void* d_out, int out_size) {
    const int*   rows_s = (const int*)d_in[0];
    const int*   cols_s = (const int*)d_in[1];
    const float* vals_s = (const float*)d_in[2];
    const int*   rows_t = (const int*)d_in[3];
    const int*   cols_t = (const int*)d_in[4];
    const float* vals_t = (const float*)d_in[5];
    const float* gamma  = (const float*)d_in[6];
    float* out = (float*)d_out;

    const int Es = in_sizes[0];
    const int Et = in_sizes[3];

    // K1: full-chip fill + folded hist
    k1_fill_hist<<<2368, 256>>>(rows_s, vals_s, Es, rows_t, vals_t, Et,
                                gamma, out);

    // K2: reciprocals (+ rowsum re-zero for replay)
    k2_finalize<<<(NN + 255) / 256, 256>>>();

    // K3: scatter, wide grid for atomic MLP
    k3_scatter<<<2048, 256>>>(rows_s, cols_s, vals_s, Es,
                              rows_t, cols_t, vals_t, Et, gamma, out);
}